// round 12
// baseline (speedup 1.0000x reference)
#include <cuda_runtime.h>
#include <math.h>

#define NN    8192
#define NL    16
#define NE    (NN * 128)         /* 1048576 edges per layer */
#define EV    (NE / 4)           /* 262144 int4 edge-vectors */
#define NR    16                 /* accumulator replicas (L2 decontention) */
#define NOUT  16
#define EOUT  (NN * NOUT)        /* 131072 output edges */

// Replicated scatter accumulators (512 KB -> spreads over LTS partitions),
// reduced node values, output logit accumulator. Scratch via __device__ (no
// allocs). Invariant: g_acc is all-zero at entry to every kernel_launch
// (zero-initialized at load; every reduce_kernel re-zeroes what it read).
__device__ float g_acc[NR][NN];
__device__ float g_val[NN];
__device__ float g_oacc[NOUT];

__device__ __forceinline__ float lrelu(float v) { return v >= 0.f ? v : 0.01f * v; }

// One hidden layer: stage vin into smem, scatter-add 1M edges into 16 replicated
// accumulators (warp w -> replica w). Grid: 256 CTAs x 512 threads, 2 int4
// edge-vectors per thread, edge loads front-batched before the staging barrier.
// Warp 0 of CTA 0 also (re)zeroes the logit accumulator — harmless every layer,
// ordered before out_kernel by stream order.
__global__ void __launch_bounds__(512, 3) layer_kernel(
    const int4*   __restrict__ src,
    const int4*   __restrict__ dst,
    const float4* __restrict__ w,
    const float*  __restrict__ vin)
{
    __shared__ float s_vals[NN];
    const int tid  = threadIdx.x;
    const int base = blockIdx.x * 1024 + tid;

    // Prefetch this thread's 8 edges (streaming) before the staging barrier.
    int4   es0 = __ldcs(&src[base]);       int4   es1 = __ldcs(&src[base + 512]);
    int4   ed0 = __ldcs(&dst[base]);       int4   ed1 = __ldcs(&dst[base + 512]);
    float4 ew0 = __ldcs(&w  [base]);       float4 ew1 = __ldcs(&w  [base + 512]);

    if (blockIdx.x == 0 && tid < NOUT) g_oacc[tid] = 0.f;

    // Stage node values (already activated by reduce_kernel / raw x for layer 0).
    const float4* vin4 = (const float4*)vin;
    float4* s4 = (float4*)s_vals;
    #pragma unroll
    for (int k = 0; k < 4; ++k) {
        int i = tid + k * 512;
        s4[i] = vin4[i];
    }
    __syncthreads();

    // Warp -> replica mapping (16 warps per CTA, NR = 16).
    float* __restrict__ out = &g_acc[tid >> 5][0];

    atomicAdd(&out[ed0.x], s_vals[es0.x] * ew0.x);
    atomicAdd(&out[ed0.y], s_vals[es0.y] * ew0.y);
    atomicAdd(&out[ed0.z], s_vals[es0.z] * ew0.z);
    atomicAdd(&out[ed0.w], s_vals[es0.w] * ew0.w);
    atomicAdd(&out[ed1.x], s_vals[es1.x] * ew1.x);
    atomicAdd(&out[ed1.y], s_vals[es1.y] * ew1.y);
    atomicAdd(&out[ed1.z], s_vals[es1.z] * ew1.z);
    atomicAdd(&out[ed1.w], s_vals[es1.w] * ew1.w);
}

// Fold the 16 replicas into g_val (with activation) and re-zero them for the
// next layer. 8 CTAs x 256 threads = 2048 threads, one float4 column each:
// 16 independent L2-direct loads, zero in-pass. ~1 MB L2-resident traffic.
__global__ void __launch_bounds__(256) reduce_kernel() {
    const int i = blockIdx.x * blockDim.x + threadIdx.x;   // float4 col < 2048
    const float4 zero = make_float4(0.f, 0.f, 0.f, 0.f);
    float4 s = zero;
    #pragma unroll
    for (int r = 0; r < NR; ++r) {
        float4 v = __ldcg(&((const float4*)g_acc[r])[i]);
        ((float4*)g_acc[r])[i] = zero;
        s.x += v.x; s.y += v.y; s.z += v.z; s.w += v.w;
    }
    ((float4*)g_val)[i] = make_float4(lrelu(s.x), lrelu(s.y), lrelu(s.z), lrelu(s.w));
}

// Output layer: 131072 edges into 16 logits. Per-CTA smem bins, one global
// atomic merge per bin per CTA. g_val is already activated.
__global__ void __launch_bounds__(256) out_kernel(
    const int*   __restrict__ osrc,
    const int*   __restrict__ odst,
    const float* __restrict__ ow)
{
    __shared__ float s_acc[NOUT];
    if (threadIdx.x < NOUT) s_acc[threadIdx.x] = 0.f;
    __syncthreads();

    const int g  = blockIdx.x * blockDim.x + threadIdx.x;
    const int gs = gridDim.x * blockDim.x;
    for (int i = g; i < EOUT; i += gs) {
        atomicAdd(&s_acc[odst[i]], g_val[osrc[i]] * ow[i]);
    }
    __syncthreads();
    if (threadIdx.x < NOUT) atomicAdd(&g_oacc[threadIdx.x], s_acc[threadIdx.x]);
}

// lrelu + softmax over the 16 logits; one warp.
__global__ void softmax_kernel(float* __restrict__ out) {
    const int t = threadIdx.x;                  // 32 threads
    float v = (t < NOUT) ? lrelu(g_oacc[t]) : -INFINITY;
    float m = v;
    #pragma unroll
    for (int o = 8; o > 0; o >>= 1) m = fmaxf(m, __shfl_xor_sync(0xffffffffu, m, o));
    float e = (t < NOUT) ? __expf(v - m) : 0.f;
    float s = e;
    #pragma unroll
    for (int o = 8; o > 0; o >>= 1) s += __shfl_xor_sync(0xffffffffu, s, o);
    if (t < NOUT) out[t] = e / s;
}

extern "C" void kernel_launch(void* const* d_in, const int* in_sizes, int n_in,
                              void* d_out, int out_size)
{
    // metadata order: x, edge_w, out_w, edge_src, edge_dst, out_src, out_dst
    const float* x        = (const float*)d_in[0];
    const float* edge_w   = (const float*)d_in[1];
    const float* out_w    = (const float*)d_in[2];
    const int*   edge_src = (const int*)  d_in[3];
    const int*   edge_dst = (const int*)  d_in[4];
    const int*   out_src  = (const int*)  d_in[5];
    const int*   out_dst  = (const int*)  d_in[6];
    float* out = (float*)d_out;

    float* val = nullptr;
    cudaGetSymbolAddress((void**)&val, g_val);   // capture-safe, not a stream op

    for (int l = 0; l < NL; ++l) {
        const float* vin = (l == 0) ? x : val;
        const size_t off = (size_t)l * NE;
        layer_kernel<<<256, 512>>>(
            (const int4*)(edge_src + off),
            (const int4*)(edge_dst + off),
            (const float4*)(edge_w + off),
            vin);
        reduce_kernel<<<8, 256>>>();
    }

    out_kernel<<<148, 256>>>(out_src, out_dst, out_w);
    softmax_kernel<<<1, 32>>>(out);
}

// round 13
// speedup vs baseline: 1.5530x; 1.5530x over previous
#include <cuda_runtime.h>
#include <math.h>

#define NN    8192
#define NL    16
#define NE    (NN * 128)         /* 1048576 edges per layer */
#define EV    (NE / 4)           /* 262144 int4 edge-vectors */
#define NR    16                 /* accumulator replicas (L2 decontention) */
#define NOUT  16
#define EOUT  (NN * NOUT)        /* 131072 output edges */

// Replicated scatter accumulators (512 KB -> spreads over LTS partitions),
// reduced node values, output logit accumulator. Scratch via __device__ (no
// allocs). Invariant: g_acc is all-zero at entry to every kernel_launch
// (zero-initialized at load; every reduce_kernel re-zeroes what it read).
__device__ float g_acc[NR][NN];
__device__ float g_val[NN];
__device__ float g_oacc[NOUT];

__device__ __forceinline__ float lrelu(float v) { return v >= 0.f ? v : 0.01f * v; }

// One hidden layer: stage vin into smem, scatter-add 1M edges into 16 replicated
// accumulators (warp w -> replica w). Grid: 256 CTAs x 512 threads, 2 int4
// edge-vectors per thread, edge loads front-batched before the staging barrier.
// CTA 0 also (re)zeroes the logit accumulator — harmless every layer, ordered
// before out_kernel by stream order.
__global__ void __launch_bounds__(512, 3) layer_kernel(
    const int4*   __restrict__ src,
    const int4*   __restrict__ dst,
    const float4* __restrict__ w,
    const float*  __restrict__ vin)
{
    __shared__ float s_vals[NN];
    const int tid  = threadIdx.x;
    const int base = blockIdx.x * 1024 + tid;

    // Prefetch this thread's 8 edges (streaming) before the staging barrier.
    int4   es0 = __ldcs(&src[base]);       int4   es1 = __ldcs(&src[base + 512]);
    int4   ed0 = __ldcs(&dst[base]);       int4   ed1 = __ldcs(&dst[base + 512]);
    float4 ew0 = __ldcs(&w  [base]);       float4 ew1 = __ldcs(&w  [base + 512]);

    if (blockIdx.x == 0 && tid < NOUT) g_oacc[tid] = 0.f;

    // Stage node values (already activated by reduce_kernel / raw x for layer 0).
    const float4* vin4 = (const float4*)vin;
    float4* s4 = (float4*)s_vals;
    #pragma unroll
    for (int k = 0; k < 4; ++k) {
        int i = tid + k * 512;
        s4[i] = vin4[i];
    }
    __syncthreads();

    // Warp -> replica mapping (16 warps per CTA, NR = 16).
    float* __restrict__ out = &g_acc[tid >> 5][0];

    atomicAdd(&out[ed0.x], s_vals[es0.x] * ew0.x);
    atomicAdd(&out[ed0.y], s_vals[es0.y] * ew0.y);
    atomicAdd(&out[ed0.z], s_vals[es0.z] * ew0.z);
    atomicAdd(&out[ed0.w], s_vals[es0.w] * ew0.w);
    atomicAdd(&out[ed1.x], s_vals[es1.x] * ew1.x);
    atomicAdd(&out[ed1.y], s_vals[es1.y] * ew1.y);
    atomicAdd(&out[ed1.z], s_vals[es1.z] * ew1.z);
    atomicAdd(&out[ed1.w], s_vals[es1.w] * ew1.w);
}

// Fold the 16 replicas into g_val (with activation) and re-zero them for the
// next layer. R5-proven shape: 32 CTAs x 256 threads = 8192 threads, one node
// per thread, 16 independent scalar loads; coalesced; ~1 MB L2-resident.
__global__ void __launch_bounds__(256) reduce_kernel() {
    const int i = blockIdx.x * blockDim.x + threadIdx.x;
    float s = 0.f;
    #pragma unroll
    for (int r = 0; r < NR; ++r) {
        s += g_acc[r][i];
        g_acc[r][i] = 0.f;
    }
    g_val[i] = lrelu(s);
}

// Output layer: 131072 edges into 16 logits. Per-CTA smem bins, one global
// atomic merge per bin per CTA. g_val is already activated.
__global__ void __launch_bounds__(256) out_kernel(
    const int*   __restrict__ osrc,
    const int*   __restrict__ odst,
    const float* __restrict__ ow)
{
    __shared__ float s_acc[NOUT];
    if (threadIdx.x < NOUT) s_acc[threadIdx.x] = 0.f;
    __syncthreads();

    const int g  = blockIdx.x * blockDim.x + threadIdx.x;
    const int gs = gridDim.x * blockDim.x;
    for (int i = g; i < EOUT; i += gs) {
        atomicAdd(&s_acc[odst[i]], g_val[osrc[i]] * ow[i]);
    }
    __syncthreads();
    if (threadIdx.x < NOUT) atomicAdd(&g_oacc[threadIdx.x], s_acc[threadIdx.x]);
}

// lrelu + softmax over the 16 logits; one warp.
__global__ void softmax_kernel(float* __restrict__ out) {
    const int t = threadIdx.x;                  // 32 threads
    float v = (t < NOUT) ? lrelu(g_oacc[t]) : -INFINITY;
    float m = v;
    #pragma unroll
    for (int o = 8; o > 0; o >>= 1) m = fmaxf(m, __shfl_xor_sync(0xffffffffu, m, o));
    float e = (t < NOUT) ? __expf(v - m) : 0.f;
    float s = e;
    #pragma unroll
    for (int o = 8; o > 0; o >>= 1) s += __shfl_xor_sync(0xffffffffu, s, o);
    if (t < NOUT) out[t] = e / s;
}

extern "C" void kernel_launch(void* const* d_in, const int* in_sizes, int n_in,
                              void* d_out, int out_size)
{
    // metadata order: x, edge_w, out_w, edge_src, edge_dst, out_src, out_dst
    const float* x        = (const float*)d_in[0];
    const float* edge_w   = (const float*)d_in[1];
    const float* out_w    = (const float*)d_in[2];
    const int*   edge_src = (const int*)  d_in[3];
    const int*   edge_dst = (const int*)  d_in[4];
    const int*   out_src  = (const int*)  d_in[5];
    const int*   out_dst  = (const int*)  d_in[6];
    float* out = (float*)d_out;

    float* val = nullptr;
    cudaGetSymbolAddress((void**)&val, g_val);   // capture-safe, not a stream op

    for (int l = 0; l < NL; ++l) {
        const float* vin = (l == 0) ? x : val;
        const size_t off = (size_t)l * NE;
        layer_kernel<<<256, 512>>>(
            (const int4*)(edge_src + off),
            (const int4*)(edge_dst + off),
            (const float4*)(edge_w + off),
            vin);
        reduce_kernel<<<32, 256>>>();
    }

    out_kernel<<<148, 256>>>(out_src, out_dst, out_w);
    softmax_kernel<<<1, 32>>>(out);
}